// round 1
// baseline (speedup 1.0000x reference)
#include <cuda_runtime.h>
#include <cuda_bf16.h>

#define NN 2048
#define NE 32768
#define DF 2048
#define TOPK 20
#define RMAXF 1e-5f
#define T_MAX 40
#define SPARSE_THRESH 384
#define LISTCAP 512

// ---------------- device scratch (no allocs allowed) ----------------
__device__ float g_P[(size_t)NN * NN];
__device__ float g_Ra[(size_t)NN * NN];
__device__ float g_Rb[(size_t)NN * NN];
__device__ float g_halfinv[NN];
__device__ int g_deg[NN], g_indeg[NN];
__device__ int g_rowptr[NN + 1], g_colptr[NN + 1];
__device__ int g_fillr[NN], g_fillc[NN];
__device__ int g_dst[NE];  // CSR out-edges (sorted per row)
__device__ int g_src[NE];  // CSC in-edges  (sorted per col)
__device__ int g_flags[T_MAX + 1];

// ---------------- init ----------------
__global__ void k_init_big() {
    int idx = blockIdx.x * blockDim.x + threadIdx.x;  // 4096 x 1024 = 4M
    g_P[idx] = 0.f;
    int r = idx >> 11, c = idx & (NN - 1);
    g_Ra[idx] = (r == c) ? 1.f : 0.f;
}

__global__ void k_init_small() {
    int t = threadIdx.x;
    for (int k = t; k < NN; k += blockDim.x) {
        g_deg[k] = 0; g_indeg[k] = 0; g_fillr[k] = 0; g_fillc[k] = 0;
    }
    for (int k = t; k <= T_MAX; k += blockDim.x) g_flags[k] = (k == 0) ? 1 : 0;
}

// ---------------- graph build ----------------
__global__ void k_count(const int* __restrict__ ei) {
    int e = blockIdx.x * blockDim.x + threadIdx.x;
    if (e >= NE) return;
    atomicAdd(&g_deg[ei[e]], 1);
    atomicAdd(&g_indeg[ei[NE + e]], 1);
}

__global__ void k_scan() {
    __shared__ int s[256];
    int t = threadIdx.x;
    for (int pass = 0; pass < 2; pass++) {
        const int* cnt = pass ? g_deg : g_indeg;
        int* ptr = pass ? g_rowptr : g_colptr;
        int base = t * 8;
        int v[8]; int sum = 0;
#pragma unroll
        for (int m = 0; m < 8; m++) { v[m] = cnt[base + m]; sum += v[m]; }
        s[t] = sum; __syncthreads();
        for (int off = 1; off < 256; off <<= 1) {
            int x = (t >= off) ? s[t - off] : 0;
            __syncthreads();
            s[t] += x;
            __syncthreads();
        }
        int excl = (t == 0) ? 0 : s[t - 1];
#pragma unroll
        for (int m = 0; m < 8; m++) { ptr[base + m] = excl; excl += v[m]; }
        if (t == 255) ptr[NN] = excl;
        __syncthreads();
    }
    int base = t * 8;
#pragma unroll
    for (int m = 0; m < 8; m++) {
        int d = g_deg[base + m];
        g_halfinv[base + m] = 0.5f / (d ? (float)d : 1.f);
    }
}

__global__ void k_fill(const int* __restrict__ ei) {
    int e = blockIdx.x * blockDim.x + threadIdx.x;
    if (e >= NE) return;
    int r = ei[e], c = ei[NE + e];
    int pr = atomicAdd(&g_fillr[r], 1);
    g_dst[g_rowptr[r] + pr] = c;
    int pc = atomicAdd(&g_fillc[c], 1);
    g_src[g_colptr[c] + pc] = r;
}

__device__ __forceinline__ void insort(int* a, int n) {
    for (int i = 1; i < n; i++) {
        int x = a[i]; int j = i - 1;
        while (j >= 0 && a[j] > x) { a[j + 1] = a[j]; j--; }
        a[j + 1] = x;
    }
}

// canonicalize adjacency-list order -> deterministic fp summation order
__global__ void k_sort() {
    int id = blockIdx.x * blockDim.x + threadIdx.x;  // 2*NN threads
    if (id >= 2 * NN) return;
    int* arr; int p0, p1;
    if (id < NN) { arr = g_src; p0 = g_colptr[id]; p1 = g_colptr[id + 1]; }
    else { arr = g_dst; p0 = g_rowptr[id - NN]; p1 = g_rowptr[id - NN + 1]; }
    int n = p1 - p0;
    if (n <= 1) return;
    if (n <= 160) {
        int buf[160];
        for (int i = 0; i < n; i++) buf[i] = arr[p0 + i];
        insort(buf, n);
        for (int i = 0; i < n; i++) arr[p0 + i] = buf[i];
    } else {
        insort(arr + p0, n);  // unreachable for this distribution; correctness fallback
    }
}

// ---------------- push iteration ----------------
// R_out[i,j] = (R[i,j] < t ? R[i,j] : 0) + sum_{k in in(j), R[i,k]>=t} R[i,k]*0.5/deg[k]
// P[i,k]   += 0.5*R[i,k]   where R[i,k] >= t
__global__ void __launch_bounds__(256) k_iter(int it) {
    if (g_flags[it] == 0) return;  // converged: cheap skip
    const float* __restrict__ Rin = (it & 1) ? g_Rb : g_Ra;
    float* __restrict__ Rout = (it & 1) ? g_Ra : g_Rb;
    __shared__ float pushv[NN];   // masked push * (0.5/deg)
    __shared__ float keep[NN];    // retained residual (also scatter accumulator)
    __shared__ int list[LISTCAP];
    __shared__ int cnt;
    __shared__ int anyflag;
    int t = threadIdx.x;
    for (int i = blockIdx.x; i < NN; i += gridDim.x) {
        if (t == 0) { cnt = 0; anyflag = 0; }
        __syncthreads();
        const float* rrow = Rin + (size_t)i * NN;
        float* prow = g_P + (size_t)i * NN;
        float* orow = Rout + (size_t)i * NN;
#pragma unroll
        for (int m = 0; m < 8; m++) {
            int k = t + m * 256;
            float r = rrow[k];
            bool push = (r >= RMAXF);
            keep[k] = push ? 0.f : r;
            pushv[k] = push ? r * g_halfinv[k] : 0.f;
            if (push) {
                prow[k] += 0.5f * r;
                int pos = atomicAdd(&cnt, 1);
                if (pos < LISTCAP) list[pos] = k;
            }
        }
        __syncthreads();
        int c = cnt;
        bool any = false;
        if (c == 0) {
            // nothing pushed: R unchanged, no flag contribution
#pragma unroll
            for (int m = 0; m < 8; m++) { int j = t + m * 256; orow[j] = keep[j]; }
        } else if (c <= SPARSE_THRESH) {
            // scatter via CSR out-edges into keep[]
            for (int l = t; l < c; l += 256) {
                int k = list[l];
                float w = pushv[k];
                int p0 = g_rowptr[k], p1 = g_rowptr[k + 1];
                for (int p = p0; p < p1; p++) atomicAdd(&keep[g_dst[p]], w);
            }
            __syncthreads();
#pragma unroll
            for (int m = 0; m < 8; m++) {
                int j = t + m * 256;
                float v = keep[j];
                orow[j] = v;
                any |= (v >= RMAXF);
            }
        } else {
            // dense path: CSC gather, no atomics
#pragma unroll
            for (int m = 0; m < 8; m++) {
                int j = t + m * 256;
                float acc = keep[j];
                int p0 = g_colptr[j], p1 = g_colptr[j + 1];
                for (int p = p0; p < p1; p++) acc += pushv[g_src[p]];
                orow[j] = acc;
                any |= (acc >= RMAXF);
            }
        }
        if (any) anyflag = 1;
        __syncthreads();
        if (t == 0 && anyflag) g_flags[it + 1] = 1;
        __syncthreads();  // shared reuse across rows
    }
}

// ---------------- fused top-k + output gemv ----------------
__global__ void __launch_bounds__(256) k_topk(const float* __restrict__ X,
                                              float* __restrict__ out) {
    __shared__ float pv[NN];
    __shared__ float rv[256];
    __shared__ int ri[256];
    __shared__ float topv[TOPK];
    __shared__ int topi[TOPK];
    int i = blockIdx.x, t = threadIdx.x;
    const float* prow = g_P + (size_t)i * NN;
#pragma unroll
    for (int m = 0; m < 8; m++) { int k = t + m * 256; pv[k] = prow[k]; }
    __syncthreads();
    for (int r = 0; r < TOPK; r++) {
        float bv = -1.f; int bi = NN;
#pragma unroll
        for (int m = 0; m < 8; m++) {
            int k = t + m * 256;
            float v = pv[k];
            if (v > bv || (v == bv && k < bi)) { bv = v; bi = k; }
        }
        rv[t] = bv; ri[t] = bi;
        __syncthreads();
        for (int s = 128; s > 0; s >>= 1) {
            if (t < s) {
                float v2 = rv[t + s]; int i2 = ri[t + s];
                if (v2 > rv[t] || (v2 == rv[t] && i2 < ri[t])) { rv[t] = v2; ri[t] = i2; }
            }
            __syncthreads();
        }
        if (t == 0) { topv[r] = rv[0]; topi[r] = ri[0]; pv[ri[0]] = -2.f; }
        __syncthreads();
    }
    float* orow = out + (size_t)i * DF;
#pragma unroll
    for (int m = 0; m < 8; m++) {
        int c = t + m * 256;
        float acc = 0.f;
#pragma unroll
        for (int r = 0; r < TOPK; r++)
            acc += topv[r] * X[(size_t)topi[r] * DF + c];
        orow[c] = acc;
    }
}

// ---------------- launch ----------------
extern "C" void kernel_launch(void* const* d_in, const int* in_sizes, int n_in,
                              void* d_out, int out_size) {
    // metadata order: node_feats (f32, 4M), edge_index (i32, 65536). Guard by size.
    const float* X;
    const int* ei;
    if (in_sizes[0] == 2 * NE) { ei = (const int*)d_in[0]; X = (const float*)d_in[1]; }
    else { X = (const float*)d_in[0]; ei = (const int*)d_in[1]; }
    float* out = (float*)d_out;

    k_init_big<<<(NN * NN) / 1024, 1024>>>();
    k_init_small<<<1, 1024>>>();
    k_count<<<NE / 256, 256>>>(ei);
    k_scan<<<1, 256>>>();
    k_fill<<<NE / 256, 256>>>(ei);
    k_sort<<<(2 * NN) / 256, 256>>>();
    for (int it = 0; it < T_MAX; it++) k_iter<<<1024, 256>>>(it);
    k_topk<<<NN, 256>>>(X, out);
}